// round 11
// baseline (speedup 1.0000x reference)
#include <cuda_runtime.h>
#include <cstdint>

// TtLlamaRotary: out[n,s,:] = x[n,s,:] @ R[s,:,:]
//   xq [8,128,128], xk [1,128,128], rot [128,128,128], out concat (9,128,128)
//
// Grid (128 s, 2 d-halves); block 256 = 16 h-groups x 16 threads; thread owns
// 4 output columns. Two CTAs co-resident per SM so their serial phases
// (prefetch-wait / compute / reduce) overlap; 8-warp barriers.
// R slice (8 x float4) prefetched into registers before the x-staging barrier.
// Issue-minimized inner loop: one LDS.128 feeds 2 h-steps (duplicated float2
// pairs), STS.128 staging, f32x2 accumulation and reduction.

#define SEQ_LEN 128
#define HEAD_DIM 128
#define NQ 8
#define NROWS 9
#define DTILE 64
#define TPG 16                        // threads per h-group (4 cols each)
#define NGROUPS 16
#define HCHUNK 8                      // 128 / 16
#define NTHREADS 256

// dynamic smem layout (bytes)
#define SM_X     0                           // 9*128*8 = 9216 (dup float2)
#define SM_PART  9216                        // 16*9*64*4 = 36864
#define SM_TOTAL (SM_PART + 36864)           // 46080

__global__ __launch_bounds__(NTHREADS, 2)
void rotary_kernel(const float* __restrict__ xq,
                   const float* __restrict__ xk,
                   const float* __restrict__ rot,
                   float* __restrict__ out) {
    extern __shared__ char smem[];
    float2* xs2  = (float2*)(smem + SM_X);      // [9][128] duplicated
    float*  part = (float*)(smem + SM_PART);    // [16][9][64]

    const int s   = blockIdx.x;
    const int dh  = blockIdx.y;       // d half 0/1
    const int tid = threadIdx.x;
    const int g   = tid / TPG;        // h-group 0..15
    const int t   = tid % TPG;        // 4-col slot 0..15

    // ---- Prefetch R slice into registers (overlaps x staging) ----
    const float4* __restrict__ R4 =
        (const float4*)rot + (size_t)s * (HEAD_DIM * HEAD_DIM / 4) + dh * (DTILE / 4) + t;
    float4 rv[HCHUNK];
    #pragma unroll
    for (int h = 0; h < HCHUNK; h++)
        rv[h] = R4[(size_t)(g * HCHUNK + h) * (HEAD_DIM / 4)];

    // ---- Stage x rows, duplicated float2 via STS.128 ----
    // 9 rows x 32 float4 = 288 chunks over 256 threads.
    for (int idx = tid; idx < NROWS * (HEAD_DIM / 4); idx += NTHREADS) {
        const int n = idx >> 5;
        const int c = idx & 31;
        const float4 v = (n < NQ)
            ? *(const float4*)(xq + ((size_t)(n * SEQ_LEN + s) * HEAD_DIM) + c * 4)
            : *(const float4*)(xk + ((size_t)s * HEAD_DIM) + c * 4);
        *(float4*)&xs2[n * HEAD_DIM + c * 4 + 0] = make_float4(v.x, v.x, v.y, v.y);
        *(float4*)&xs2[n * HEAD_DIM + c * 4 + 2] = make_float4(v.z, v.z, v.w, v.w);
    }
    __syncthreads();

    // ---- Accumulate: 4 h-pairs x 9 rows; LDS.128 feeds 2 h-steps ----
    unsigned long long acc01[NROWS], acc23[NROWS];
    #pragma unroll
    for (int n = 0; n < NROWS; n++) { acc01[n] = 0ull; acc23[n] = 0ull; }

    #pragma unroll
    for (int hp = 0; hp < HCHUNK / 2; hp++) {
        const int hh = g * HCHUNK + hp * 2;
        unsigned long long rA01, rA23, rB01, rB23;
        asm("mov.b64 %0, {%1, %2};" : "=l"(rA01) : "f"(rv[hp*2].x),   "f"(rv[hp*2].y));
        asm("mov.b64 %0, {%1, %2};" : "=l"(rA23) : "f"(rv[hp*2].z),   "f"(rv[hp*2].w));
        asm("mov.b64 %0, {%1, %2};" : "=l"(rB01) : "f"(rv[hp*2+1].x), "f"(rv[hp*2+1].y));
        asm("mov.b64 %0, {%1, %2};" : "=l"(rB23) : "f"(rv[hp*2+1].z), "f"(rv[hp*2+1].w));
        #pragma unroll
        for (int n = 0; n < NROWS; n++) {
            // one LDS.128: {x_h, x_h, x_h1, x_h1}
            const ulonglong2 xp = *(const ulonglong2*)&xs2[n * HEAD_DIM + hh];
            asm("fma.rn.f32x2 %0, %1, %2, %0;" : "+l"(acc01[n]) : "l"(xp.x), "l"(rA01));
            asm("fma.rn.f32x2 %0, %1, %2, %0;" : "+l"(acc23[n]) : "l"(xp.x), "l"(rA23));
            asm("fma.rn.f32x2 %0, %1, %2, %0;" : "+l"(acc01[n]) : "l"(xp.y), "l"(rB01));
            asm("fma.rn.f32x2 %0, %1, %2, %0;" : "+l"(acc23[n]) : "l"(xp.y), "l"(rB23));
        }
    }

    // ---- Write partials (STS.128) ----
    #pragma unroll
    for (int n = 0; n < NROWS; n++) {
        float a0, a1, a2, a3;
        asm("mov.b64 {%0, %1}, %2;" : "=f"(a0), "=f"(a1) : "l"(acc01[n]));
        asm("mov.b64 {%0, %1}, %2;" : "=f"(a2), "=f"(a3) : "l"(acc23[n]));
        *(float4*)&part[(g * NROWS + n) * DTILE + t * 4] =
            make_float4(a0, a1, a2, a3);
    }
    __syncthreads();

    // ---- Reduce 16 partials with f32x2 adds: 9 x 16 float4 = 144 outputs ----
    if (tid < NROWS * (DTILE / 4)) {
        const int n = tid / (DTILE / 4);
        const int c = tid % (DTILE / 4);
        unsigned long long v01 = 0ull, v23 = 0ull;
        #pragma unroll
        for (int gg = 0; gg < NGROUPS; gg++) {
            const ulonglong2 p =
                *(const ulonglong2*)&part[(gg * NROWS + n) * DTILE + c * 4];
            asm("add.rn.f32x2 %0, %0, %1;" : "+l"(v01) : "l"(p.x));
            asm("add.rn.f32x2 %0, %0, %1;" : "+l"(v23) : "l"(p.y));
        }
        float a0, a1, a2, a3;
        asm("mov.b64 {%0, %1}, %2;" : "=f"(a0), "=f"(a1) : "l"(v01));
        asm("mov.b64 {%0, %1}, %2;" : "=f"(a2), "=f"(a3) : "l"(v23));
        // n==8 lands exactly at the xk output block (uniform indexing).
        const size_t o = (size_t)(n * SEQ_LEN + s) * HEAD_DIM + dh * DTILE + c * 4;
        *(float4*)(out + o) = make_float4(a0, a1, a2, a3);
    }
}

extern "C" void kernel_launch(void* const* d_in, const int* in_sizes, int n_in,
                              void* d_out, int out_size) {
    const float* xq  = (const float*)d_in[0];
    const float* xk  = (const float*)d_in[1];
    const float* rot = (const float*)d_in[2];
    float* out = (float*)d_out;

    cudaFuncSetAttribute(rotary_kernel,
                         cudaFuncAttributeMaxDynamicSharedMemorySize, SM_TOTAL);
    dim3 grid(SEQ_LEN, 2);
    rotary_kernel<<<grid, NTHREADS, SM_TOTAL>>>(xq, xk, rot, out);
}

// round 12
// speedup vs baseline: 1.3527x; 1.3527x over previous
#include <cuda_runtime.h>
#include <cstdint>

// TtLlamaRotary: out[n,s,:] = x[n,s,:] @ R[s,:,:]
//   xq [8,128,128], xk [1,128,128], rot [128,128,128], out concat (9,128,128)
//
// One CTA per seq position s (grid 128, block 512 = 16 h-groups x 32 threads).
// Thread owns 4 output columns; x staged once per CTA (min traffic 9.57 MB).
// R slice (8 x float4) prefetched into registers before the x-staging barrier.
// Issue-minimized inner loop: one LDS.128 feeds 2 h-steps, f32x2 FMA/adds.
// Boundary phases (staging / reduction) balanced across ALL 512 threads at
// float2 granularity so barrier release isn't gated on a 288-thread subset.

#define SEQ_LEN 128
#define HEAD_DIM 128
#define NQ 8
#define NROWS 9
#define TPG 32
#define NGROUPS 16
#define HCHUNK 8
#define NTHREADS 512
#define NCHUNK2 (NROWS * (HEAD_DIM / 2))     // 576 float2 chunks

// dynamic smem layout (bytes)
#define SM_X     0                           // 9*128*8 = 9216 (dup float2)
#define SM_PART  9216                        // 16*9*128*4 = 73728
#define SM_TOTAL (SM_PART + 73728)           // 82944

__global__ __launch_bounds__(NTHREADS, 1)
void rotary_kernel(const float* __restrict__ xq,
                   const float* __restrict__ xk,
                   const float* __restrict__ rot,
                   float* __restrict__ out) {
    extern __shared__ char smem[];
    float2* xs2  = (float2*)(smem + SM_X);      // [9][128] duplicated
    float*  part = (float*)(smem + SM_PART);    // [16][9][128]

    const int s   = blockIdx.x;
    const int tid = threadIdx.x;
    const int g   = tid / TPG;        // h-group 0..15
    const int t   = tid % TPG;        // 4-col slot 0..31

    // ---- Prefetch R slice into registers (overlaps x staging) ----
    const float4* __restrict__ R4 =
        (const float4*)rot + (size_t)s * (HEAD_DIM * HEAD_DIM / 4) + t;
    float4 rv[HCHUNK];
    #pragma unroll
    for (int h = 0; h < HCHUNK; h++)
        rv[h] = R4[(size_t)(g * HCHUNK + h) * (HEAD_DIM / 4)];

    // ---- Stage x ONCE: 576 float2 chunks over 512 threads ----
    // chunk idx -> row n = idx/64, float2 c = idx%64.
    #pragma unroll
    for (int idx = tid; idx < NCHUNK2; idx += NTHREADS) {
        const int n = idx >> 6;
        const int c = idx & 63;
        const float2 v = (n < NQ)
            ? *(const float2*)(xq + ((size_t)(n * SEQ_LEN + s) * HEAD_DIM) + c * 2)
            : *(const float2*)(xk + ((size_t)s * HEAD_DIM) + c * 2);
        // duplicated pair -> one STS.128
        *(float4*)&xs2[n * HEAD_DIM + c * 2] = make_float4(v.x, v.x, v.y, v.y);
    }
    __syncthreads();

    // ---- Accumulate: 4 h-pairs x 9 rows; LDS.128 feeds 2 h-steps ----
    unsigned long long acc01[NROWS], acc23[NROWS];
    #pragma unroll
    for (int n = 0; n < NROWS; n++) { acc01[n] = 0ull; acc23[n] = 0ull; }

    #pragma unroll
    for (int hp = 0; hp < HCHUNK / 2; hp++) {
        const int hh = g * HCHUNK + hp * 2;
        unsigned long long rA01, rA23, rB01, rB23;
        asm("mov.b64 %0, {%1, %2};" : "=l"(rA01) : "f"(rv[hp*2].x),   "f"(rv[hp*2].y));
        asm("mov.b64 %0, {%1, %2};" : "=l"(rA23) : "f"(rv[hp*2].z),   "f"(rv[hp*2].w));
        asm("mov.b64 %0, {%1, %2};" : "=l"(rB01) : "f"(rv[hp*2+1].x), "f"(rv[hp*2+1].y));
        asm("mov.b64 %0, {%1, %2};" : "=l"(rB23) : "f"(rv[hp*2+1].z), "f"(rv[hp*2+1].w));
        #pragma unroll
        for (int n = 0; n < NROWS; n++) {
            // one LDS.128: {x_h, x_h, x_h1, x_h1}
            const ulonglong2 xp = *(const ulonglong2*)&xs2[n * HEAD_DIM + hh];
            asm("fma.rn.f32x2 %0, %1, %2, %0;" : "+l"(acc01[n]) : "l"(xp.x), "l"(rA01));
            asm("fma.rn.f32x2 %0, %1, %2, %0;" : "+l"(acc23[n]) : "l"(xp.x), "l"(rA23));
            asm("fma.rn.f32x2 %0, %1, %2, %0;" : "+l"(acc01[n]) : "l"(xp.y), "l"(rB01));
            asm("fma.rn.f32x2 %0, %1, %2, %0;" : "+l"(acc23[n]) : "l"(xp.y), "l"(rB23));
        }
    }

    // ---- Write partials (STS.128) ----
    #pragma unroll
    for (int n = 0; n < NROWS; n++) {
        float a0, a1, a2, a3;
        asm("mov.b64 {%0, %1}, %2;" : "=f"(a0), "=f"(a1) : "l"(acc01[n]));
        asm("mov.b64 {%0, %1}, %2;" : "=f"(a2), "=f"(a3) : "l"(acc23[n]));
        *(float4*)&part[(g * NROWS + n) * HEAD_DIM + t * 4] =
            make_float4(a0, a1, a2, a3);
    }
    __syncthreads();

    // ---- Reduce 16 partials: 576 float2 outputs over 512 threads ----
    #pragma unroll
    for (int idx = tid; idx < NCHUNK2; idx += NTHREADS) {
        const int n = idx >> 6;
        const int c = idx & 63;
        unsigned long long v = 0ull;
        #pragma unroll
        for (int gg = 0; gg < NGROUPS; gg++) {
            const unsigned long long p =
                *(const unsigned long long*)&part[(gg * NROWS + n) * HEAD_DIM + c * 2];
            asm("add.rn.f32x2 %0, %0, %1;" : "+l"(v) : "l"(p));
        }
        float a0, a1;
        asm("mov.b64 {%0, %1}, %2;" : "=f"(a0), "=f"(a1) : "l"(v));
        // n==8 lands exactly at the xk output block (uniform indexing).
        const size_t o = (size_t)(n * SEQ_LEN + s) * HEAD_DIM + c * 2;
        *(float2*)(out + o) = make_float2(a0, a1);
    }
}

extern "C" void kernel_launch(void* const* d_in, const int* in_sizes, int n_in,
                              void* d_out, int out_size) {
    const float* xq  = (const float*)d_in[0];
    const float* xk  = (const float*)d_in[1];
    const float* rot = (const float*)d_in[2];
    float* out = (float*)d_out;

    cudaFuncSetAttribute(rotary_kernel,
                         cudaFuncAttributeMaxDynamicSharedMemorySize, SM_TOTAL);
    rotary_kernel<<<SEQ_LEN, NTHREADS, SM_TOTAL>>>(xq, xk, rot, out);
}